// round 4
// baseline (speedup 1.0000x reference)
#include <cuda_runtime.h>
#include <cuda_bf16.h>

#define Nn   50000
#define Ee   800000
#define F_IN 128
#define HID  64
#define Ll   3
#define Gg   512
#define BN_EPS 1e-5f
#define INVN (1.0f / 50000.0f)

#define EDGE_BLOCKS  ((Ee + 255) / 256)            // 3125
#define STAT_BLOCKS  256
#define SETUP_BLOCKS (EDGE_BLOCKS + STAT_BLOCKS)   // 3381
#define GEMM_BLOCKS  ((Nn + 63) / 64)              // 782
#define GATHER_BLOCKS 512
#define SCAN_T 1024
#define SCAN_CH ((Nn + SCAN_T - 1) / SCAN_T)       // 49

// ---------------- scratch (static device arrays; zero-initialized) ---------
__device__ float g_h[Nn * HID];        // activations (post-relu)
__device__ float g_z[Nn * HID];        // post-linear (BN folded)
__device__ float g_Wp[F_IN * HID];     // folded weight
__device__ float g_c[HID];             // folded bias row
__device__ float g_sum[F_IN];          // x stats accumulators (zero invariant)
__device__ float g_sumsq[F_IN];
__device__ float g_s2[HID];            // h stats accumulators (zero invariant)
__device__ float g_q2[HID];
__device__ int   g_degout[Nn];         // zero invariant
__device__ int   g_degin[Nn];          // zero invariant
__device__ float g_dis[Nn];
__device__ int   g_off[Nn + 1];
__device__ int   g_cursor[Nn];
__device__ int   g_csr[Ee];
__device__ int   g_ctr;                // last-block counter (zero invariant)

// ---------------- helpers ----------------------------------------------------
__device__ __forceinline__ void red_add_v4(float* addr, float4 v) {
    asm volatile("red.global.add.v4.f32 [%0], {%1, %2, %3, %4};"
                 :: "l"(addr), "f"(v.x), "f"(v.y), "f"(v.z), "f"(v.w)
                 : "memory");
}

// BN fold executed by one block (256 threads): reads sums, computes
// g_Wp = diag(s)W and g_c = t@W (+blin), zeroes the sums (invariant).
__device__ __forceinline__ void do_fold(const float* __restrict__ gamma,
                                        const float* __restrict__ beta,
                                        const float* __restrict__ W,
                                        const float* __restrict__ blin,
                                        int K, float* sums, float* sqs) {
    __shared__ float s_s[F_IN], s_t[F_IN];
    int t = threadIdx.x;
    if (t < K) {
        float mu  = sums[t] * INVN;
        float var = fmaxf(sqs[t] * INVN - mu * mu, 0.f);
        float sc  = gamma[t] * rsqrtf(var + BN_EPS);
        s_s[t] = sc;
        s_t[t] = beta[t] - mu * sc;
        sums[t] = 0.f;   // restore zero invariant
        sqs[t]  = 0.f;
    }
    __syncthreads();
    for (int i = t; i < K * HID; i += 256)
        g_Wp[i] = s_s[i >> 6] * W[i];
    if (t < HID) {
        float c = blin ? blin[t] : 0.f;
        for (int k = 0; k < K; k++) c += s_t[k] * W[k * HID + t];
        g_c[t] = c;
    }
}

// ---------------- setup: edge degree count + x stats + feat fold ------------
__global__ void __launch_bounds__(256)
setup_kernel(const int* __restrict__ src, const int* __restrict__ dst,
             const float* __restrict__ x,
             const float* __restrict__ gamma, const float* __restrict__ beta,
             const float* __restrict__ W, const float* __restrict__ blin) {
    int b = blockIdx.x, t = threadIdx.x;
    if (b < EDGE_BLOCKS) {
        int e = b * 256 + t;
        if (e < Ee) {
            atomicAdd(&g_degout[src[e]], 1);
            atomicAdd(&g_degin[dst[e]], 1);
        }
    } else {
        // x stats: col = t&127, half = t>>7
        int b2 = b - EDGE_BLOCKS;
        int col = t & 127, half = t >> 7;
        float s = 0.f, ss = 0.f;
        for (int r = b2 * 2 + half; r < Nn; r += STAT_BLOCKS * 2) {
            float v = x[(long)r * F_IN + col];
            s += v; ss += v * v;
        }
        __shared__ float sh0[256], sh1[256];
        sh0[t] = s; sh1[t] = ss;
        __syncthreads();
        if (half == 0) {
            s += sh0[128 + col]; ss += sh1[128 + col];
            atomicAdd(&g_sum[col], s);
            atomicAdd(&g_sumsq[col], ss);
        }
    }
    // last-block fold
    __shared__ int isLast;
    __threadfence();
    if (t == 0) isLast = (atomicAdd(&g_ctr, 1) == SETUP_BLOCKS - 1);
    __syncthreads();
    if (isLast) {
        do_fold(gamma, beta, W, blin, F_IN, g_sum, g_sumsq);
        if (t == 0) g_ctr = 0;
    }
}

// ---------------- single-block scan of degin -> off/cursor, plus dis --------
__global__ void __launch_bounds__(SCAN_T)
scan_dis_kernel() {
    __shared__ int sh[SCAN_T];
    int t = threadIdx.x;
    int lo = t * SCAN_CH;
    int hi = min(lo + SCAN_CH, Nn);
    int s = 0;
    for (int i = lo; i < hi; i++) s += g_degin[i];
    sh[t] = s;
    __syncthreads();
    for (int o = 1; o < SCAN_T; o <<= 1) {
        int v = (t >= o) ? sh[t - o] : 0;
        __syncthreads();
        sh[t] += v;
        __syncthreads();
    }
    int acc = sh[t] - s;   // exclusive base
    for (int i = lo; i < hi; i++) {
        g_off[i] = acc; g_cursor[i] = acc;
        acc += g_degin[i];
        g_dis[i] = rsqrtf((float)(g_degout[i] + 1));
    }
    if (t == SCAN_T - 1) g_off[Nn] = acc;
}

// ---------------- fill CSR + restore deg zero invariant ---------------------
__global__ void __launch_bounds__(256)
fill_kernel(const int* __restrict__ src, const int* __restrict__ dst) {
    int e = blockIdx.x * blockDim.x + threadIdx.x;
    if (e < Ee) {
        int pos = atomicAdd(&g_cursor[dst[e]], 1);
        g_csr[pos] = src[e];
    }
    int v = blockIdx.x * blockDim.x + threadIdx.x;
    if (v < Nn) { g_degin[v] = 0; g_degout[v] = 0; }
}

// ---------------- tiled GEMM -------------------------------------------------
// FEAT: g_h = relu(A@Wp + c), col stats -> g_s2/g_q2, last block folds layer 0.
// LAYER: g_z = A@Wp + c.
template <int K, bool FEAT>
__global__ void __launch_bounds__(256)
gemm_kernel(const float* __restrict__ A,
            const float* __restrict__ gamma, const float* __restrict__ beta,
            const float* __restrict__ Wnext) {
    __shared__ float As[64 * 64];
    __shared__ float Wsm[64 * 64];
    const int t  = threadIdx.x;
    const int tx = t & 15;
    const int ty = t >> 4;
    const int rowBase = blockIdx.x * 64;

    float4 acc0 = {0,0,0,0}, acc1 = {0,0,0,0}, acc2 = {0,0,0,0}, acc3 = {0,0,0,0};

    for (int kt = 0; kt < K; kt += 64) {
        #pragma unroll
        for (int i = t; i < 64 * 16; i += 256) {
            int r = i >> 4, c4 = i & 15;
            int gr = rowBase + r;
            float4 v = {0,0,0,0};
            if (gr < Nn) v = *(const float4*)(A + (long)gr * K + kt + 4 * c4);
            ((float4*)As)[i] = v;
        }
        #pragma unroll
        for (int i = t; i < 64 * 16; i += 256) {
            int r = i >> 4, c4 = i & 15;
            ((float4*)Wsm)[i] = *(const float4*)(g_Wp + (long)(kt + r) * 64 + 4 * c4);
        }
        __syncthreads();

        #pragma unroll
        for (int k4 = 0; k4 < 64; k4 += 4) {
            float4 a0 = ((const float4*)As)[(4 * ty + 0) * 16 + (k4 >> 2)];
            float4 a1 = ((const float4*)As)[(4 * ty + 1) * 16 + (k4 >> 2)];
            float4 a2 = ((const float4*)As)[(4 * ty + 2) * 16 + (k4 >> 2)];
            float4 a3 = ((const float4*)As)[(4 * ty + 3) * 16 + (k4 >> 2)];
            float4 w0 = ((const float4*)Wsm)[(k4 + 0) * 16 + tx];
            float4 w1 = ((const float4*)Wsm)[(k4 + 1) * 16 + tx];
            float4 w2 = ((const float4*)Wsm)[(k4 + 2) * 16 + tx];
            float4 w3 = ((const float4*)Wsm)[(k4 + 3) * 16 + tx];
            #define FMA4(ACC, AV)                                              \
                ACC.x += AV.x * w0.x; ACC.y += AV.x * w0.y;                    \
                ACC.z += AV.x * w0.z; ACC.w += AV.x * w0.w;                    \
                ACC.x += AV.y * w1.x; ACC.y += AV.y * w1.y;                    \
                ACC.z += AV.y * w1.z; ACC.w += AV.y * w1.w;                    \
                ACC.x += AV.z * w2.x; ACC.y += AV.z * w2.y;                    \
                ACC.z += AV.z * w2.z; ACC.w += AV.z * w2.w;                    \
                ACC.x += AV.w * w3.x; ACC.y += AV.w * w3.y;                    \
                ACC.z += AV.w * w3.z; ACC.w += AV.w * w3.w;
            FMA4(acc0, a0) FMA4(acc1, a1) FMA4(acc2, a2) FMA4(acc3, a3)
            #undef FMA4
        }
        __syncthreads();
    }

    float4 cv = *(const float4*)(g_c + 4 * tx);
    float4 accs[4] = {acc0, acc1, acc2, acc3};
    float4 ls = {0,0,0,0}, lq = {0,0,0,0};
    #pragma unroll
    for (int i = 0; i < 4; i++) {
        int gr = rowBase + 4 * ty + i;
        if (gr >= Nn) continue;
        float4 v = accs[i];
        v.x += cv.x; v.y += cv.y; v.z += cv.z; v.w += cv.w;
        if (FEAT) {
            v.x = fmaxf(v.x, 0.f); v.y = fmaxf(v.y, 0.f);
            v.z = fmaxf(v.z, 0.f); v.w = fmaxf(v.w, 0.f);
            *(float4*)(g_h + (long)gr * 64 + 4 * tx) = v;
            ls.x += v.x; ls.y += v.y; ls.z += v.z; ls.w += v.w;
            lq.x += v.x * v.x; lq.y += v.y * v.y;
            lq.z += v.z * v.z; lq.w += v.w * v.w;
        } else {
            *(float4*)(g_z + (long)gr * 64 + 4 * tx) = v;
        }
    }
    if (FEAT) {
        __syncthreads();
        ((float4*)As)[t]  = ls;
        ((float4*)Wsm)[t] = lq;
        __syncthreads();
        if (ty == 0) {
            #pragma unroll
            for (int j = 1; j < 16; j++) {
                float4 a = ((float4*)As)[j * 16 + tx];
                float4 b = ((float4*)Wsm)[j * 16 + tx];
                ls.x += a.x; ls.y += a.y; ls.z += a.z; ls.w += a.w;
                lq.x += b.x; lq.y += b.y; lq.z += b.z; lq.w += b.w;
            }
            red_add_v4(g_s2 + 4 * tx, ls);
            red_add_v4(g_q2 + 4 * tx, lq);
        }
        __shared__ int isLast;
        __threadfence();
        if (t == 0) isLast = (atomicAdd(&g_ctr, 1) == GEMM_BLOCKS - 1);
        __syncthreads();
        if (isLast) {
            do_fold(gamma, beta, Wnext, nullptr, HID, g_s2, g_q2);
            if (t == 0) g_ctr = 0;
        }
    }
}

// ---------------- CSR gather aggregation ------------------------------------
// h_i = relu(dis_i*(dis_i*z_i + sum_{s in in(i)} dis_s*z_s) + b)
// MODE 0: write g_h, col stats, last block folds next layer.
// MODE 1: pool into gout (by batch).
template <int MODE>
__global__ void __launch_bounds__(256)
gather_kernel(const float* __restrict__ bias,
              const int* __restrict__ batch,
              float* __restrict__ gout,
              const float* __restrict__ gamma, const float* __restrict__ beta,
              const float* __restrict__ Wnext) {
    const int t    = threadIdx.x;
    const int c    = t & 15;
    const int slot = t >> 4;
    float4 b4 = *(const float4*)(bias + 4 * c);
    float4 ls = {0,0,0,0}, lq = {0,0,0,0};

    for (int base = blockIdx.x * 16; base < Nn; base += gridDim.x * 16) {
        int i = base + slot;
        if (i < Nn) {
            int st = __ldg(g_off + i), en = __ldg(g_off + i + 1);
            float di = __ldg(g_dis + i);
            float4 acc = *(const float4*)(g_z + (long)i * 64 + 4 * c);
            acc.x *= di; acc.y *= di; acc.z *= di; acc.w *= di;
            int e = st;
            for (; e + 3 < en; e += 4) {          // MLP-4 unroll
                int s0 = __ldg(g_csr + e + 0);
                int s1 = __ldg(g_csr + e + 1);
                int s2 = __ldg(g_csr + e + 2);
                int s3 = __ldg(g_csr + e + 3);
                float w0 = __ldg(g_dis + s0);
                float w1 = __ldg(g_dis + s1);
                float w2 = __ldg(g_dis + s2);
                float w3 = __ldg(g_dis + s3);
                float4 v0 = *(const float4*)(g_z + (long)s0 * 64 + 4 * c);
                float4 v1 = *(const float4*)(g_z + (long)s1 * 64 + 4 * c);
                float4 v2 = *(const float4*)(g_z + (long)s2 * 64 + 4 * c);
                float4 v3 = *(const float4*)(g_z + (long)s3 * 64 + 4 * c);
                acc.x += w0 * v0.x; acc.y += w0 * v0.y;
                acc.z += w0 * v0.z; acc.w += w0 * v0.w;
                acc.x += w1 * v1.x; acc.y += w1 * v1.y;
                acc.z += w1 * v1.z; acc.w += w1 * v1.w;
                acc.x += w2 * v2.x; acc.y += w2 * v2.y;
                acc.z += w2 * v2.z; acc.w += w2 * v2.w;
                acc.x += w3 * v3.x; acc.y += w3 * v3.y;
                acc.z += w3 * v3.z; acc.w += w3 * v3.w;
            }
            for (; e < en; e++) {
                int s = __ldg(g_csr + e);
                float w = __ldg(g_dis + s);
                float4 v = *(const float4*)(g_z + (long)s * 64 + 4 * c);
                acc.x += w * v.x; acc.y += w * v.y;
                acc.z += w * v.z; acc.w += w * v.w;
            }
            float4 h;
            h.x = fmaxf(di * acc.x + b4.x, 0.f);
            h.y = fmaxf(di * acc.y + b4.y, 0.f);
            h.z = fmaxf(di * acc.z + b4.z, 0.f);
            h.w = fmaxf(di * acc.w + b4.w, 0.f);
            if (MODE == 0) {
                *(float4*)(g_h + (long)i * 64 + 4 * c) = h;
                ls.x += h.x; ls.y += h.y; ls.z += h.z; ls.w += h.w;
                lq.x += h.x * h.x; lq.y += h.y * h.y;
                lq.z += h.z * h.z; lq.w += h.w * h.w;
            } else {
                int g = __ldg(batch + i);
                red_add_v4(gout + (long)g * 64 + 4 * c, h);
            }
        }
    }

    if (MODE == 0) {
        __shared__ float4 shS[256], shQ[256];
        shS[t] = ls; shQ[t] = lq;
        __syncthreads();
        if (slot == 0) {
            #pragma unroll
            for (int j = 1; j < 16; j++) {
                float4 a = shS[j * 16 + c], b = shQ[j * 16 + c];
                ls.x += a.x; ls.y += a.y; ls.z += a.z; ls.w += a.w;
                lq.x += b.x; lq.y += b.y; lq.z += b.z; lq.w += b.w;
            }
            red_add_v4(g_s2 + 4 * c, ls);
            red_add_v4(g_q2 + 4 * c, lq);
        }
        __shared__ int isLast;
        __threadfence();
        if (t == 0) isLast = (atomicAdd(&g_ctr, 1) == GATHER_BLOCKS - 1);
        __syncthreads();
        if (isLast) {
            do_fold(gamma, beta, Wnext, nullptr, HID, g_s2, g_q2);
            if (t == 0) g_ctr = 0;
        }
    }
}

// ---------------- host-side symbol resolution -------------------------------
static float* sym_h() {
    static float* p = nullptr;
    if (!p) cudaGetSymbolAddress((void**)&p, g_h);
    return p;
}

// ---------------- launch ------------------------------------------------------
extern "C" void kernel_launch(void* const* d_in, const int* in_sizes, int n_in,
                              void* d_out, int out_size) {
    const float* x         = (const float*)d_in[0];
    const int*   ei        = (const int*)d_in[1];
    const int*   src       = ei;
    const int*   dst       = ei + Ee;
    const int*   batch     = (const int*)d_in[2];
    const float* bn_feat_g = (const float*)d_in[3];
    const float* bn_feat_b = (const float*)d_in[4];
    const float* W_feat    = (const float*)d_in[5];
    const float* b_feat    = (const float*)d_in[6];
    const float* bn_g      = (const float*)d_in[7];
    const float* bn_b      = (const float*)d_in[8];
    const float* Ws        = (const float*)d_in[9];
    const float* bs        = (const float*)d_in[10];
    float* gout = (float*)d_out;

    // 1. edge degree count + x stats + feat fold (last block)
    setup_kernel<<<SETUP_BLOCKS, 256>>>(src, dst, x,
                                        bn_feat_g, bn_feat_b, W_feat, b_feat);
    // 2. scan degin -> off/cursor, dis
    scan_dis_kernel<<<1, SCAN_T>>>();
    // 3. fill CSR (+ restore deg zero invariant)
    fill_kernel<<<EDGE_BLOCKS, 256>>>(src, dst);
    // (output zeroing can happen any time before the pool gather)
    cudaMemsetAsync(gout, 0, (size_t)Gg * HID * sizeof(float));
    // 4. feat GEMM: h0 = relu(x@Wp+c); stats(h0); last block folds layer 0
    gemm_kernel<F_IN, true><<<GEMM_BLOCKS, 256>>>(x, bn_g, bn_b, Ws);
    // 5-10. three GCN layers
    for (int i = 0; i < Ll; i++) {
        gemm_kernel<HID, false><<<GEMM_BLOCKS, 256>>>(sym_h(), nullptr,
                                                      nullptr, nullptr);
        if (i < Ll - 1) {
            gather_kernel<0><<<GATHER_BLOCKS, 256>>>(
                bs + i * HID, nullptr, nullptr,
                bn_g + (i + 1) * HID, bn_b + (i + 1) * HID,
                Ws + (long)(i + 1) * HID * HID);
        } else {
            gather_kernel<1><<<GATHER_BLOCKS, 256>>>(
                bs + i * HID, batch, gout, nullptr, nullptr, nullptr);
        }
    }
}

// round 5
// speedup vs baseline: 1.9416x; 1.9416x over previous
#include <cuda_runtime.h>
#include <cuda_fp16.h>

#define Nn   50000
#define Ee   800000
#define F_IN 128
#define HID  64
#define Ll   3
#define Gg   512
#define BN_EPS 1e-5f
#define INVN (1.0f / 50000.0f)

#define EDGE_BLOCKS  ((Ee + 255) / 256)            // 3125
#define STAT_BLOCKS  256
#define SETUP_BLOCKS (EDGE_BLOCKS + STAT_BLOCKS)
#define GEMM_BLOCKS  ((Nn + 63) / 64)              // 782
#define GATHER_GRID  ((Nn + 15) / 16)              // 3125
#define SCAN_T   512
#define SCAN_E   2048
#define SCAN_NB  ((Nn + SCAN_E - 1) / SCAN_E)      // 25

// ---------------- scratch (static device arrays; zero-initialized) ---------
// Zero invariants maintained across graph replays:
//   g_degin/g_degout re-zeroed by fill; g_sum/g_sumsq zeroed by feat fold;
//   g_s2/g_q2 zeroed by layer folds.
__device__ float  g_h[Nn * HID];       // activations (post-relu)
__device__ __half g_zh[Nn * HID];      // dis-prescaled post-linear, fp16
__device__ float  g_Wp[F_IN * HID];    // folded weight
__device__ float  g_c[HID];            // folded bias row
__device__ float  g_sum[F_IN];         // x stats (zero invariant)
__device__ float  g_sumsq[F_IN];
__device__ float  g_s2[HID];           // h stats (zero invariant)
__device__ float  g_q2[HID];
__device__ int    g_degout[Nn];        // zero invariant
__device__ int    g_degin[Nn];         // zero invariant
__device__ float  g_dis[Nn];
__device__ int    g_off[Nn + 1];
__device__ int    g_cursor[Nn];
__device__ int    g_csr[Ee];
__device__ int    g_bsum[SCAN_NB];
__device__ int    g_bbase[SCAN_NB];

// ---------------- helpers ----------------------------------------------------
__device__ __forceinline__ void red_add_v4(float* addr, float4 v) {
    asm volatile("red.global.add.v4.f32 [%0], {%1, %2, %3, %4};"
                 :: "l"(addr), "f"(v.x), "f"(v.y), "f"(v.z), "f"(v.w)
                 : "memory");
}

__device__ __forceinline__ float4 h4_to_f4(uint2 u) {
    __half2 a = *(__half2*)&u.x;
    __half2 b = *(__half2*)&u.y;
    float2 fa = __half22float2(a);
    float2 fb = __half22float2(b);
    return make_float4(fa.x, fa.y, fb.x, fb.y);
}

// ---------------- setup: edge degree count + x column stats -----------------
__global__ void __launch_bounds__(256)
setup_kernel(const int* __restrict__ src, const int* __restrict__ dst,
             const float* __restrict__ x) {
    int b = blockIdx.x, t = threadIdx.x;
    if (b < EDGE_BLOCKS) {
        int e = b * 256 + t;
        if (e < Ee) {
            atomicAdd(&g_degout[src[e]], 1);
            atomicAdd(&g_degin[dst[e]], 1);
        }
    } else {
        int b2 = b - EDGE_BLOCKS;
        int col = t & 127, half = t >> 7;
        float s = 0.f, ss = 0.f;
        for (int r = b2 * 2 + half; r < Nn; r += STAT_BLOCKS * 2) {
            float v = x[(long)r * F_IN + col];
            s += v; ss += v * v;
        }
        __shared__ float sh0[256], sh1[256];
        sh0[t] = s; sh1[t] = ss;
        __syncthreads();
        if (half == 0) {
            s += sh0[128 + col]; ss += sh1[128 + col];
            atomicAdd(&g_sum[col], s);
            atomicAdd(&g_sumsq[col], ss);
        }
    }
}

// ---------------- scan (multi-block, 3 kernels) ------------------------------
__global__ void scan1_kernel() {
    __shared__ int sh[SCAN_T];
    int t = threadIdx.x, b = blockIdx.x;
    int s = 0;
    #pragma unroll
    for (int j = 0; j < 4; j++) {
        int i = b * SCAN_E + t + j * SCAN_T;
        if (i < Nn) s += g_degin[i];
    }
    sh[t] = s; __syncthreads();
    for (int o = SCAN_T / 2; o > 0; o >>= 1) {
        if (t < o) sh[t] += sh[t + o];
        __syncthreads();
    }
    if (t == 0) g_bsum[b] = sh[0];
}

__global__ void scan2_kernel() {
    if (threadIdx.x == 0) {
        int acc = 0;
        for (int b = 0; b < SCAN_NB; b++) { g_bbase[b] = acc; acc += g_bsum[b]; }
        g_off[Nn] = acc;
    }
}

__global__ void scan3_kernel() {   // local scan + cursor + dis
    __shared__ int sh[SCAN_T];
    int t = threadIdx.x, b = blockIdx.x;
    int base = b * SCAN_E + t * 4;
    int d0 = 0, d1 = 0, d2 = 0, d3 = 0;
    if (base + 0 < Nn) d0 = g_degin[base + 0];
    if (base + 1 < Nn) d1 = g_degin[base + 1];
    if (base + 2 < Nn) d2 = g_degin[base + 2];
    if (base + 3 < Nn) d3 = g_degin[base + 3];
    int tsum = d0 + d1 + d2 + d3;
    sh[t] = tsum; __syncthreads();
    for (int o = 1; o < SCAN_T; o <<= 1) {
        int v = (t >= o) ? sh[t - o] : 0;
        __syncthreads();
        sh[t] += v;
        __syncthreads();
    }
    int excl = sh[t] - tsum + g_bbase[b];
    int o0 = excl, o1 = o0 + d0, o2 = o1 + d1, o3 = o2 + d2;
    if (base + 0 < Nn) {
        g_off[base + 0] = o0; g_cursor[base + 0] = o0;
        g_dis[base + 0] = rsqrtf((float)(g_degout[base + 0] + 1));
    }
    if (base + 1 < Nn) {
        g_off[base + 1] = o1; g_cursor[base + 1] = o1;
        g_dis[base + 1] = rsqrtf((float)(g_degout[base + 1] + 1));
    }
    if (base + 2 < Nn) {
        g_off[base + 2] = o2; g_cursor[base + 2] = o2;
        g_dis[base + 2] = rsqrtf((float)(g_degout[base + 2] + 1));
    }
    if (base + 3 < Nn) {
        g_off[base + 3] = o3; g_cursor[base + 3] = o3;
        g_dis[base + 3] = rsqrtf((float)(g_degout[base + 3] + 1));
    }
}

// ---------------- fill CSR + restore deg zero invariant ---------------------
__global__ void __launch_bounds__(256)
fill_kernel(const int* __restrict__ src, const int* __restrict__ dst) {
    int e = blockIdx.x * blockDim.x + threadIdx.x;
    if (e < Ee) {
        int pos = atomicAdd(&g_cursor[dst[e]], 1);
        g_csr[pos] = src[e];
    }
    if (e < Nn) { g_degin[e] = 0; g_degout[e] = 0; }
}

// ---------------- fold: BN -> (Wp, c); zero accumulators --------------------
// fromX=1: K=128 stats from g_sum/g_sumsq; else K=64 stats from g_s2/g_q2.
__global__ void __launch_bounds__(256)
fold_kernel(const float* __restrict__ gamma, const float* __restrict__ beta,
            const float* __restrict__ W, const float* __restrict__ blin,
            int K, int fromX) {
    __shared__ float s_s[F_IN], s_t[F_IN];
    int t = threadIdx.x;
    float* sums = fromX ? g_sum : g_s2;
    float* sqs  = fromX ? g_sumsq : g_q2;
    if (t < K) {
        float mu  = sums[t] * INVN;
        float var = fmaxf(sqs[t] * INVN - mu * mu, 0.f);
        float sc  = gamma[t] * rsqrtf(var + BN_EPS);
        s_s[t] = sc;
        s_t[t] = beta[t] - mu * sc;
        sums[t] = 0.f;     // restore zero invariant
        sqs[t]  = 0.f;
    }
    __syncthreads();
    for (int i = t; i < K * HID; i += 256)
        g_Wp[i] = s_s[i >> 6] * W[i];
    if (t < HID) {
        float c = blin ? blin[t] : 0.f;
        for (int k = 0; k < K; k++) c += s_t[k] * W[k * HID + t];
        g_c[t] = c;
    }
}

// ---------------- tiled GEMM -------------------------------------------------
// FEAT : g_h = relu(A@Wp + c); column stats -> g_s2/g_q2 (red.v4).
// LAYER: g_zh = fp16( dis_row * (A@Wp + c) ).
template <int K, bool FEAT>
__global__ void __launch_bounds__(256)
gemm_kernel(const float* __restrict__ A) {
    __shared__ float As[64 * 64];
    __shared__ float Wsm[64 * 64];
    const int t  = threadIdx.x;
    const int tx = t & 15;
    const int ty = t >> 4;
    const int rowBase = blockIdx.x * 64;

    float4 acc0 = {0,0,0,0}, acc1 = {0,0,0,0}, acc2 = {0,0,0,0}, acc3 = {0,0,0,0};

    for (int kt = 0; kt < K; kt += 64) {
        #pragma unroll
        for (int i = t; i < 64 * 16; i += 256) {
            int r = i >> 4, c4 = i & 15;
            int gr = rowBase + r;
            float4 v = {0,0,0,0};
            if (gr < Nn) v = *(const float4*)(A + (long)gr * K + kt + 4 * c4);
            ((float4*)As)[i] = v;
        }
        #pragma unroll
        for (int i = t; i < 64 * 16; i += 256) {
            int r = i >> 4, c4 = i & 15;
            ((float4*)Wsm)[i] = *(const float4*)(g_Wp + (long)(kt + r) * 64 + 4 * c4);
        }
        __syncthreads();

        #pragma unroll
        for (int k4 = 0; k4 < 64; k4 += 4) {
            float4 a0 = ((const float4*)As)[(4 * ty + 0) * 16 + (k4 >> 2)];
            float4 a1 = ((const float4*)As)[(4 * ty + 1) * 16 + (k4 >> 2)];
            float4 a2 = ((const float4*)As)[(4 * ty + 2) * 16 + (k4 >> 2)];
            float4 a3 = ((const float4*)As)[(4 * ty + 3) * 16 + (k4 >> 2)];
            float4 w0 = ((const float4*)Wsm)[(k4 + 0) * 16 + tx];
            float4 w1 = ((const float4*)Wsm)[(k4 + 1) * 16 + tx];
            float4 w2 = ((const float4*)Wsm)[(k4 + 2) * 16 + tx];
            float4 w3 = ((const float4*)Wsm)[(k4 + 3) * 16 + tx];
            #define FMA4(ACC, AV)                                              \
                ACC.x += AV.x * w0.x; ACC.y += AV.x * w0.y;                    \
                ACC.z += AV.x * w0.z; ACC.w += AV.x * w0.w;                    \
                ACC.x += AV.y * w1.x; ACC.y += AV.y * w1.y;                    \
                ACC.z += AV.y * w1.z; ACC.w += AV.y * w1.w;                    \
                ACC.x += AV.z * w2.x; ACC.y += AV.z * w2.y;                    \
                ACC.z += AV.z * w2.z; ACC.w += AV.z * w2.w;                    \
                ACC.x += AV.w * w3.x; ACC.y += AV.w * w3.y;                    \
                ACC.z += AV.w * w3.z; ACC.w += AV.w * w3.w;
            FMA4(acc0, a0) FMA4(acc1, a1) FMA4(acc2, a2) FMA4(acc3, a3)
            #undef FMA4
        }
        __syncthreads();
    }

    float4 cv = *(const float4*)(g_c + 4 * tx);
    float4 accs[4] = {acc0, acc1, acc2, acc3};
    float4 ls = {0,0,0,0}, lq = {0,0,0,0};
    #pragma unroll
    for (int i = 0; i < 4; i++) {
        int gr = rowBase + 4 * ty + i;
        if (gr >= Nn) continue;
        float4 v = accs[i];
        v.x += cv.x; v.y += cv.y; v.z += cv.z; v.w += cv.w;
        if (FEAT) {
            v.x = fmaxf(v.x, 0.f); v.y = fmaxf(v.y, 0.f);
            v.z = fmaxf(v.z, 0.f); v.w = fmaxf(v.w, 0.f);
            *(float4*)(g_h + (long)gr * 64 + 4 * tx) = v;
            ls.x += v.x; ls.y += v.y; ls.z += v.z; ls.w += v.w;
            lq.x += v.x * v.x; lq.y += v.y * v.y;
            lq.z += v.z * v.z; lq.w += v.w * v.w;
        } else {
            float di = __ldg(g_dis + gr);
            __half2 p0 = __floats2half2_rn(di * v.x, di * v.y);
            __half2 p1 = __floats2half2_rn(di * v.z, di * v.w);
            uint2 u;
            u.x = *(unsigned*)&p0;
            u.y = *(unsigned*)&p1;
            *(uint2*)(g_zh + (long)gr * 64 + 4 * tx) = u;
        }
    }
    if (FEAT) {
        __syncthreads();
        ((float4*)As)[t]  = ls;
        ((float4*)Wsm)[t] = lq;
        __syncthreads();
        if (ty == 0) {
            #pragma unroll
            for (int j = 1; j < 16; j++) {
                float4 a = ((float4*)As)[j * 16 + tx];
                float4 b = ((float4*)Wsm)[j * 16 + tx];
                ls.x += a.x; ls.y += a.y; ls.z += a.z; ls.w += a.w;
                lq.x += b.x; lq.y += b.y; lq.z += b.z; lq.w += b.w;
            }
            red_add_v4(g_s2 + 4 * tx, ls);
            red_add_v4(g_q2 + 4 * tx, lq);
        }
    }
}

// ---------------- CSR gather aggregation (fp16 zs, pre-scaled) --------------
// out_i = dis_i * (zs_i + sum_{s in in(i)} zs_s);  h = relu(out + b)
// MODE 0: write g_h + stats (red.v4).  MODE 1: pool into gout (by batch).
template <int MODE>
__global__ void __launch_bounds__(256)
gather_kernel(const float* __restrict__ bias,
              const int* __restrict__ batch,
              float* __restrict__ gout) {
    const int t    = threadIdx.x;
    const int c    = t & 15;
    const int slot = t >> 4;
    const int i    = blockIdx.x * 16 + slot;
    float4 b4 = *(const float4*)(bias + 4 * c);
    float4 ls = {0,0,0,0}, lq = {0,0,0,0};

    if (i < Nn) {
        int st = __ldg(g_off + i), en = __ldg(g_off + i + 1);
        float di = __ldg(g_dis + i);
        const __half* zb = g_zh;
        float4 acc = h4_to_f4(__ldg((const uint2*)(zb + (long)i * 64) + c));
        int e = st;
        for (; e + 3 < en; e += 4) {
            int s0 = __ldg(g_csr + e + 0);
            int s1 = __ldg(g_csr + e + 1);
            int s2 = __ldg(g_csr + e + 2);
            int s3 = __ldg(g_csr + e + 3);
            uint2 u0 = __ldg((const uint2*)(zb + (long)s0 * 64) + c);
            uint2 u1 = __ldg((const uint2*)(zb + (long)s1 * 64) + c);
            uint2 u2 = __ldg((const uint2*)(zb + (long)s2 * 64) + c);
            uint2 u3 = __ldg((const uint2*)(zb + (long)s3 * 64) + c);
            float4 v0 = h4_to_f4(u0), v1 = h4_to_f4(u1);
            float4 v2 = h4_to_f4(u2), v3 = h4_to_f4(u3);
            acc.x += v0.x + v1.x + v2.x + v3.x;
            acc.y += v0.y + v1.y + v2.y + v3.y;
            acc.z += v0.z + v1.z + v2.z + v3.z;
            acc.w += v0.w + v1.w + v2.w + v3.w;
        }
        for (; e < en; e++) {
            int s = __ldg(g_csr + e);
            float4 v = h4_to_f4(__ldg((const uint2*)(zb + (long)s * 64) + c));
            acc.x += v.x; acc.y += v.y; acc.z += v.z; acc.w += v.w;
        }
        float4 h;
        h.x = fmaxf(di * acc.x + b4.x, 0.f);
        h.y = fmaxf(di * acc.y + b4.y, 0.f);
        h.z = fmaxf(di * acc.z + b4.z, 0.f);
        h.w = fmaxf(di * acc.w + b4.w, 0.f);
        if (MODE == 0) {
            *(float4*)(g_h + (long)i * 64 + 4 * c) = h;
            ls.x = h.x; ls.y = h.y; ls.z = h.z; ls.w = h.w;
            lq.x = h.x * h.x; lq.y = h.y * h.y;
            lq.z = h.z * h.z; lq.w = h.w * h.w;
        } else {
            int g = __ldg(batch + i);
            red_add_v4(gout + (long)g * 64 + 4 * c, h);
        }
    }

    if (MODE == 0) {
        __shared__ float4 shS[256], shQ[256];
        shS[t] = ls; shQ[t] = lq;
        __syncthreads();
        if (slot == 0) {
            #pragma unroll
            for (int j = 1; j < 16; j++) {
                float4 a = shS[j * 16 + c], b = shQ[j * 16 + c];
                ls.x += a.x; ls.y += a.y; ls.z += a.z; ls.w += a.w;
                lq.x += b.x; lq.y += b.y; lq.z += b.z; lq.w += b.w;
            }
            red_add_v4(g_s2 + 4 * c, ls);
            red_add_v4(g_q2 + 4 * c, lq);
        }
    }
}

// ---------------- host-side symbol resolution -------------------------------
static float* sym_h() {
    static float* p = nullptr;
    if (!p) cudaGetSymbolAddress((void**)&p, g_h);
    return p;
}

// ---------------- launch ------------------------------------------------------
extern "C" void kernel_launch(void* const* d_in, const int* in_sizes, int n_in,
                              void* d_out, int out_size) {
    const float* x         = (const float*)d_in[0];
    const int*   ei        = (const int*)d_in[1];
    const int*   src       = ei;
    const int*   dst       = ei + Ee;
    const int*   batch     = (const int*)d_in[2];
    const float* bn_feat_g = (const float*)d_in[3];
    const float* bn_feat_b = (const float*)d_in[4];
    const float* W_feat    = (const float*)d_in[5];
    const float* b_feat    = (const float*)d_in[6];
    const float* bn_g      = (const float*)d_in[7];
    const float* bn_b      = (const float*)d_in[8];
    const float* Ws        = (const float*)d_in[9];
    const float* bs        = (const float*)d_in[10];
    float* gout = (float*)d_out;

    // 1. degree count + x stats
    setup_kernel<<<SETUP_BLOCKS, 256>>>(src, dst, x);
    // 2-4. scan degin -> off/cursor (+dis)
    scan1_kernel<<<SCAN_NB, SCAN_T>>>();
    scan2_kernel<<<1, 32>>>();
    scan3_kernel<<<SCAN_NB, SCAN_T>>>();
    // 5. fill CSR (+ deg re-zero)
    fill_kernel<<<EDGE_BLOCKS, 256>>>(src, dst);
    cudaMemsetAsync(gout, 0, (size_t)Gg * HID * sizeof(float));
    // 6. feat fold + GEMM (h0 + stats)
    fold_kernel<<<1, 256>>>(bn_feat_g, bn_feat_b, W_feat, b_feat, F_IN, 1);
    gemm_kernel<F_IN, true><<<GEMM_BLOCKS, 256>>>(x);
    // 7. three GCN layers
    for (int i = 0; i < Ll; i++) {
        fold_kernel<<<1, 256>>>(bn_g + i * HID, bn_b + i * HID,
                                Ws + (long)i * HID * HID, nullptr, HID, 0);
        gemm_kernel<HID, false><<<GEMM_BLOCKS, 256>>>(sym_h());
        if (i < Ll - 1)
            gather_kernel<0><<<GATHER_GRID, 256>>>(bs + i * HID, nullptr,
                                                   nullptr);
        else
            gather_kernel<1><<<GATHER_GRID, 256>>>(bs + i * HID, batch, gout);
    }
}

// round 6
// speedup vs baseline: 2.0135x; 1.0370x over previous
#include <cuda_runtime.h>
#include <cuda_fp16.h>

#define Nn   50000
#define Ee   800000
#define F_IN 128
#define HID  64
#define Ll   3
#define Gg   512
#define BN_EPS 1e-5f
#define INVN (1.0f / 50000.0f)

#define EDGE_BLOCKS  ((Ee + 255) / 256)            // 3125
#define STAT_BLOCKS  256
#define SETUP_BLOCKS (EDGE_BLOCKS + STAT_BLOCKS)
#define GEMM_BLOCKS  ((Nn + 127) / 128)            // 391
#define GATHER_GRID  ((Nn + 15) / 16)              // 3125
#define SCAN_T   512
#define SCAN_E   2048
#define SCAN_NB  ((Nn + SCAN_E - 1) / SCAN_E)      // 25

// ---------------- scratch (static device arrays; zero-initialized) ---------
__device__ float  g_h[Nn * HID];       // activations (post-relu)
__device__ __half g_zh[Nn * HID];      // dis-prescaled post-linear, fp16
__device__ float  g_Wp[F_IN * HID];    // folded weight
__device__ float  g_c[HID];            // folded bias row
__device__ float  g_sum[F_IN];         // x stats (zero invariant)
__device__ float  g_sumsq[F_IN];
__device__ float  g_s2[HID];           // h stats (zero invariant)
__device__ float  g_q2[HID];
__device__ int    g_degout[Nn];        // zero invariant
__device__ int    g_degin[Nn];         // zero invariant
__device__ float  g_dis[Nn];
__device__ int    g_off[Nn + 1];
__device__ int    g_cursor[Nn];
__device__ int    g_csr[Ee];
__device__ int    g_bsum[SCAN_NB];
__device__ int    g_bbase[SCAN_NB];

// ---------------- helpers ----------------------------------------------------
__device__ __forceinline__ void red_add_v4(float* addr, float4 v) {
    asm volatile("red.global.add.v4.f32 [%0], {%1, %2, %3, %4};"
                 :: "l"(addr), "f"(v.x), "f"(v.y), "f"(v.z), "f"(v.w)
                 : "memory");
}

__device__ __forceinline__ float4 h4_to_f4(uint2 u) {
    __half2 a = *(__half2*)&u.x;
    __half2 b = *(__half2*)&u.y;
    float2 fa = __half22float2(a);
    float2 fb = __half22float2(b);
    return make_float4(fa.x, fa.y, fb.x, fb.y);
}

// ---------------- setup: edge degree count + x column stats -----------------
__global__ void __launch_bounds__(256)
setup_kernel(const int* __restrict__ src, const int* __restrict__ dst,
             const float* __restrict__ x) {
    int b = blockIdx.x, t = threadIdx.x;
    if (b < EDGE_BLOCKS) {
        int e = b * 256 + t;
        if (e < Ee) {
            atomicAdd(&g_degout[src[e]], 1);
            atomicAdd(&g_degin[dst[e]], 1);
        }
    } else {
        int b2 = b - EDGE_BLOCKS;
        int col = t & 127, half = t >> 7;
        float s = 0.f, ss = 0.f;
        for (int r = b2 * 2 + half; r < Nn; r += STAT_BLOCKS * 2) {
            float v = x[(long)r * F_IN + col];
            s += v; ss += v * v;
        }
        __shared__ float sh0[256], sh1[256];
        sh0[t] = s; sh1[t] = ss;
        __syncthreads();
        if (half == 0) {
            s += sh0[128 + col]; ss += sh1[128 + col];
            atomicAdd(&g_sum[col], s);
            atomicAdd(&g_sumsq[col], ss);
        }
    }
}

// ---------------- scan (multi-block, 3 kernels) ------------------------------
__global__ void scan1_kernel() {
    __shared__ int sh[SCAN_T];
    int t = threadIdx.x, b = blockIdx.x;
    int s = 0;
    #pragma unroll
    for (int j = 0; j < 4; j++) {
        int i = b * SCAN_E + t + j * SCAN_T;
        if (i < Nn) s += g_degin[i];
    }
    sh[t] = s; __syncthreads();
    for (int o = SCAN_T / 2; o > 0; o >>= 1) {
        if (t < o) sh[t] += sh[t + o];
        __syncthreads();
    }
    if (t == 0) g_bsum[b] = sh[0];
}

__global__ void scan2_kernel() {
    if (threadIdx.x == 0) {
        int acc = 0;
        for (int b = 0; b < SCAN_NB; b++) { g_bbase[b] = acc; acc += g_bsum[b]; }
        g_off[Nn] = acc;
    }
}

__global__ void scan3_kernel() {   // local scan + cursor + dis
    __shared__ int sh[SCAN_T];
    int t = threadIdx.x, b = blockIdx.x;
    int base = b * SCAN_E + t * 4;
    int d0 = 0, d1 = 0, d2 = 0, d3 = 0;
    if (base + 0 < Nn) d0 = g_degin[base + 0];
    if (base + 1 < Nn) d1 = g_degin[base + 1];
    if (base + 2 < Nn) d2 = g_degin[base + 2];
    if (base + 3 < Nn) d3 = g_degin[base + 3];
    int tsum = d0 + d1 + d2 + d3;
    sh[t] = tsum; __syncthreads();
    for (int o = 1; o < SCAN_T; o <<= 1) {
        int v = (t >= o) ? sh[t - o] : 0;
        __syncthreads();
        sh[t] += v;
        __syncthreads();
    }
    int excl = sh[t] - tsum + g_bbase[b];
    int o0 = excl, o1 = o0 + d0, o2 = o1 + d1, o3 = o2 + d2;
    if (base + 0 < Nn) {
        g_off[base + 0] = o0; g_cursor[base + 0] = o0;
        g_dis[base + 0] = rsqrtf((float)(g_degout[base + 0] + 1));
    }
    if (base + 1 < Nn) {
        g_off[base + 1] = o1; g_cursor[base + 1] = o1;
        g_dis[base + 1] = rsqrtf((float)(g_degout[base + 1] + 1));
    }
    if (base + 2 < Nn) {
        g_off[base + 2] = o2; g_cursor[base + 2] = o2;
        g_dis[base + 2] = rsqrtf((float)(g_degout[base + 2] + 1));
    }
    if (base + 3 < Nn) {
        g_off[base + 3] = o3; g_cursor[base + 3] = o3;
        g_dis[base + 3] = rsqrtf((float)(g_degout[base + 3] + 1));
    }
}

// ---------------- fill CSR + restore deg zero invariant ---------------------
__global__ void __launch_bounds__(256)
fill_kernel(const int* __restrict__ src, const int* __restrict__ dst) {
    int e = blockIdx.x * blockDim.x + threadIdx.x;
    if (e < Ee) {
        int pos = atomicAdd(&g_cursor[dst[e]], 1);
        g_csr[pos] = src[e];
    }
    if (e < Nn) { g_degin[e] = 0; g_degout[e] = 0; }
}

// ---------------- fold: BN -> (Wp, c); zero accumulators --------------------
__global__ void __launch_bounds__(256)
fold_kernel(const float* __restrict__ gamma, const float* __restrict__ beta,
            const float* __restrict__ W, const float* __restrict__ blin,
            int K, int fromX) {
    __shared__ float s_s[F_IN], s_t[F_IN];
    int t = threadIdx.x;
    float* sums = fromX ? g_sum : g_s2;
    float* sqs  = fromX ? g_sumsq : g_q2;
    if (t < K) {
        float mu  = sums[t] * INVN;
        float var = fmaxf(sqs[t] * INVN - mu * mu, 0.f);
        float sc  = gamma[t] * rsqrtf(var + BN_EPS);
        s_s[t] = sc;
        s_t[t] = beta[t] - mu * sc;
        sums[t] = 0.f;
        sqs[t]  = 0.f;
    }
    __syncthreads();
    for (int i = t; i < K * HID; i += 256)
        g_Wp[i] = s_s[i >> 6] * W[i];
    if (t < HID) {
        float c = blin ? blin[t] : 0.f;
        for (int k = 0; k < K; k++) c += s_t[k] * W[k * HID + t];
        g_c[t] = c;
    }
}

// ---------------- tiled GEMM: 128x64 tile, 8x4 register tiles ---------------
// FEAT : g_h = relu(A@Wp + c); column stats -> g_s2/g_q2 (red.v4).
// LAYER: g_zh = fp16( dis_row * (A@Wp + c) ).
template <int K, bool FEAT>
__global__ void __launch_bounds__(256, 2)
gemm_kernel(const float* __restrict__ A) {
    __shared__ float As[128 * 64];   // 32 KB
    __shared__ float Wsm[64 * 64];   // 16 KB
    const int t  = threadIdx.x;
    const int tx = t & 15;    // col group (4 cols)
    const int ty = t >> 4;    // row group (8 rows)
    const int rowBase = blockIdx.x * 128;

    float4 acc[8];
    #pragma unroll
    for (int i = 0; i < 8; i++) acc[i] = make_float4(0.f, 0.f, 0.f, 0.f);

    for (int kt = 0; kt < K; kt += 64) {
        // stage A tile: 128 rows x 64 k = 2048 float4, 8 per thread
        #pragma unroll
        for (int i = t; i < 128 * 16; i += 256) {
            int r = i >> 4, c4 = i & 15;
            int gr = rowBase + r;
            float4 v = {0,0,0,0};
            if (gr < Nn) v = *(const float4*)(A + (long)gr * K + kt + 4 * c4);
            ((float4*)As)[i] = v;
        }
        // stage W tile: 64 k x 64 cols = 1024 float4, 4 per thread
        #pragma unroll
        for (int i = t; i < 64 * 16; i += 256) {
            int r = i >> 4, c4 = i & 15;
            ((float4*)Wsm)[i] = *(const float4*)(g_Wp + (long)(kt + r) * 64 + 4 * c4);
        }
        __syncthreads();

        #pragma unroll
        for (int k4 = 0; k4 < 16; k4++) {
            float4 w0 = ((const float4*)Wsm)[(4 * k4 + 0) * 16 + tx];
            float4 w1 = ((const float4*)Wsm)[(4 * k4 + 1) * 16 + tx];
            float4 w2 = ((const float4*)Wsm)[(4 * k4 + 2) * 16 + tx];
            float4 w3 = ((const float4*)Wsm)[(4 * k4 + 3) * 16 + tx];
            #pragma unroll
            for (int i = 0; i < 8; i++) {
                float4 a = ((const float4*)As)[(8 * ty + i) * 16 + k4];
                acc[i].x += a.x * w0.x; acc[i].y += a.x * w0.y;
                acc[i].z += a.x * w0.z; acc[i].w += a.x * w0.w;
                acc[i].x += a.y * w1.x; acc[i].y += a.y * w1.y;
                acc[i].z += a.y * w1.z; acc[i].w += a.y * w1.w;
                acc[i].x += a.z * w2.x; acc[i].y += a.z * w2.y;
                acc[i].z += a.z * w2.z; acc[i].w += a.z * w2.w;
                acc[i].x += a.w * w3.x; acc[i].y += a.w * w3.y;
                acc[i].z += a.w * w3.z; acc[i].w += a.w * w3.w;
            }
        }
        __syncthreads();
    }

    float4 cv = *(const float4*)(g_c + 4 * tx);
    float4 ls = {0,0,0,0}, lq = {0,0,0,0};
    #pragma unroll
    for (int i = 0; i < 8; i++) {
        int gr = rowBase + 8 * ty + i;
        if (gr >= Nn) continue;
        float4 v = acc[i];
        v.x += cv.x; v.y += cv.y; v.z += cv.z; v.w += cv.w;
        if (FEAT) {
            v.x = fmaxf(v.x, 0.f); v.y = fmaxf(v.y, 0.f);
            v.z = fmaxf(v.z, 0.f); v.w = fmaxf(v.w, 0.f);
            *(float4*)(g_h + (long)gr * 64 + 4 * tx) = v;
            ls.x += v.x; ls.y += v.y; ls.z += v.z; ls.w += v.w;
            lq.x += v.x * v.x; lq.y += v.y * v.y;
            lq.z += v.z * v.z; lq.w += v.w * v.w;
        } else {
            float di = __ldg(g_dis + gr);
            __half2 p0 = __floats2half2_rn(di * v.x, di * v.y);
            __half2 p1 = __floats2half2_rn(di * v.z, di * v.w);
            uint2 u;
            u.x = *(unsigned*)&p0;
            u.y = *(unsigned*)&p1;
            *(uint2*)(g_zh + (long)gr * 64 + 4 * tx) = u;
        }
    }
    if (FEAT) {   // per-column partial stats: reduce over 16 ty groups
        __syncthreads();
        ((float4*)As)[t]          = ls;
        ((float4*)As)[256 + t]    = lq;
        __syncthreads();
        if (ty == 0) {
            #pragma unroll
            for (int j = 1; j < 16; j++) {
                float4 a = ((float4*)As)[j * 16 + tx];
                float4 b = ((float4*)As)[256 + j * 16 + tx];
                ls.x += a.x; ls.y += a.y; ls.z += a.z; ls.w += a.w;
                lq.x += b.x; lq.y += b.y; lq.z += b.z; lq.w += b.w;
            }
            red_add_v4(g_s2 + 4 * tx, ls);
            red_add_v4(g_q2 + 4 * tx, lq);
        }
    }
}

// ---------------- CSR gather aggregation (fp16 zs, pre-scaled) --------------
template <int MODE>
__global__ void __launch_bounds__(256)
gather_kernel(const float* __restrict__ bias,
              const int* __restrict__ batch,
              float* __restrict__ gout) {
    const int t    = threadIdx.x;
    const int c    = t & 15;
    const int slot = t >> 4;
    const int i    = blockIdx.x * 16 + slot;
    float4 b4 = *(const float4*)(bias + 4 * c);
    float4 ls = {0,0,0,0}, lq = {0,0,0,0};

    if (i < Nn) {
        int st = __ldg(g_off + i), en = __ldg(g_off + i + 1);
        float di = __ldg(g_dis + i);
        const __half* zb = g_zh;
        float4 acc = h4_to_f4(__ldg((const uint2*)(zb + (long)i * 64) + c));
        int e = st;
        for (; e + 3 < en; e += 4) {
            int s0 = __ldg(g_csr + e + 0);
            int s1 = __ldg(g_csr + e + 1);
            int s2 = __ldg(g_csr + e + 2);
            int s3 = __ldg(g_csr + e + 3);
            uint2 u0 = __ldg((const uint2*)(zb + (long)s0 * 64) + c);
            uint2 u1 = __ldg((const uint2*)(zb + (long)s1 * 64) + c);
            uint2 u2 = __ldg((const uint2*)(zb + (long)s2 * 64) + c);
            uint2 u3 = __ldg((const uint2*)(zb + (long)s3 * 64) + c);
            float4 v0 = h4_to_f4(u0), v1 = h4_to_f4(u1);
            float4 v2 = h4_to_f4(u2), v3 = h4_to_f4(u3);
            acc.x += v0.x + v1.x + v2.x + v3.x;
            acc.y += v0.y + v1.y + v2.y + v3.y;
            acc.z += v0.z + v1.z + v2.z + v3.z;
            acc.w += v0.w + v1.w + v2.w + v3.w;
        }
        for (; e < en; e++) {
            int s = __ldg(g_csr + e);
            float4 v = h4_to_f4(__ldg((const uint2*)(zb + (long)s * 64) + c));
            acc.x += v.x; acc.y += v.y; acc.z += v.z; acc.w += v.w;
        }
        float4 h;
        h.x = fmaxf(di * acc.x + b4.x, 0.f);
        h.y = fmaxf(di * acc.y + b4.y, 0.f);
        h.z = fmaxf(di * acc.z + b4.z, 0.f);
        h.w = fmaxf(di * acc.w + b4.w, 0.f);
        if (MODE == 0) {
            *(float4*)(g_h + (long)i * 64 + 4 * c) = h;
            ls = h;
            lq.x = h.x * h.x; lq.y = h.y * h.y;
            lq.z = h.z * h.z; lq.w = h.w * h.w;
        } else {
            int g = __ldg(batch + i);
            red_add_v4(gout + (long)g * 64 + 4 * c, h);
        }
    }

    if (MODE == 0) {
        __shared__ float4 shS[256], shQ[256];
        shS[t] = ls; shQ[t] = lq;
        __syncthreads();
        if (slot == 0) {
            #pragma unroll
            for (int j = 1; j < 16; j++) {
                float4 a = shS[j * 16 + c], b = shQ[j * 16 + c];
                ls.x += a.x; ls.y += a.y; ls.z += a.z; ls.w += a.w;
                lq.x += b.x; lq.y += b.y; lq.z += b.z; lq.w += b.w;
            }
            red_add_v4(g_s2 + 4 * c, ls);
            red_add_v4(g_q2 + 4 * c, lq);
        }
    }
}

// ---------------- host-side symbol resolution -------------------------------
static float* sym_h() {
    static float* p = nullptr;
    if (!p) cudaGetSymbolAddress((void**)&p, g_h);
    return p;
}

// ---------------- launch ------------------------------------------------------
extern "C" void kernel_launch(void* const* d_in, const int* in_sizes, int n_in,
                              void* d_out, int out_size) {
    const float* x         = (const float*)d_in[0];
    const int*   ei        = (const int*)d_in[1];
    const int*   src       = ei;
    const int*   dst       = ei + Ee;
    const int*   batch     = (const int*)d_in[2];
    const float* bn_feat_g = (const float*)d_in[3];
    const float* bn_feat_b = (const float*)d_in[4];
    const float* W_feat    = (const float*)d_in[5];
    const float* b_feat    = (const float*)d_in[6];
    const float* bn_g      = (const float*)d_in[7];
    const float* bn_b      = (const float*)d_in[8];
    const float* Ws        = (const float*)d_in[9];
    const float* bs        = (const float*)d_in[10];
    float* gout = (float*)d_out;

    setup_kernel<<<SETUP_BLOCKS, 256>>>(src, dst, x);
    scan1_kernel<<<SCAN_NB, SCAN_T>>>();
    scan2_kernel<<<1, 32>>>();
    scan3_kernel<<<SCAN_NB, SCAN_T>>>();
    fill_kernel<<<EDGE_BLOCKS, 256>>>(src, dst);
    cudaMemsetAsync(gout, 0, (size_t)Gg * HID * sizeof(float));
    fold_kernel<<<1, 256>>>(bn_feat_g, bn_feat_b, W_feat, b_feat, F_IN, 1);
    gemm_kernel<F_IN, true><<<GEMM_BLOCKS, 256>>>(x);
    for (int i = 0; i < Ll; i++) {
        fold_kernel<<<1, 256>>>(bn_g + i * HID, bn_b + i * HID,
                                Ws + (long)i * HID * HID, nullptr, HID, 0);
        gemm_kernel<HID, false><<<GEMM_BLOCKS, 256>>>(sym_h());
        if (i < Ll - 1)
            gather_kernel<0><<<GATHER_GRID, 256>>>(bs + i * HID, nullptr,
                                                   nullptr);
        else
            gather_kernel<1><<<GATHER_GRID, 256>>>(bs + i * HID, batch, gout);
    }
}

// round 7
// speedup vs baseline: 2.1809x; 1.0831x over previous
#include <cuda_runtime.h>
#include <cuda_fp16.h>

#define Nn   50000
#define Ee   800000
#define F_IN 128
#define HID  64
#define Ll   3
#define Gg   512
#define BN_EPS 1e-5f
#define INVN (1.0f / 50000.0f)

#define EDGE_BLOCKS  ((Ee + 255) / 256)            // 3125
#define STAT_BLOCKS  256
#define GEMM_BLOCKS  ((Nn + 127) / 128)            // 391
#define GATHER_GRID  ((Nn + 15) / 16)              // 3125
#define SCAN_T   512
#define SCAN_E   2048
#define SCAN_NB  ((Nn + SCAN_E - 1) / SCAN_E)      // 25

// ---------------- scratch (static device arrays; zero-initialized) ---------
__device__ float  g_h[Nn * HID];       // activations (post-relu)
__device__ __half g_zh[Nn * HID];      // dis-prescaled post-linear, fp16
__device__ float  g_Wp[F_IN * HID];    // folded weight
__device__ float  g_c[HID];            // folded bias row
__device__ float  g_sum[F_IN];         // x stats (zero invariant)
__device__ float  g_sumsq[F_IN];
__device__ float  g_s2[HID];           // h stats (zero invariant)
__device__ float  g_q2[HID];
__device__ int    g_degout[Nn];        // zero invariant
__device__ int    g_degin[Nn];         // zero invariant
__device__ float  g_dis[Nn];
__device__ int    g_off[Nn + 1];
__device__ int    g_cursor[Nn];
__device__ int    g_csr[Ee];
__device__ int    g_bsum[SCAN_NB];
__device__ int    g_bbase[SCAN_NB];

// ---------------- helpers ----------------------------------------------------
__device__ __forceinline__ void red_add_v4(float* addr, float4 v) {
    asm volatile("red.global.add.v4.f32 [%0], {%1, %2, %3, %4};"
                 :: "l"(addr), "f"(v.x), "f"(v.y), "f"(v.z), "f"(v.w)
                 : "memory");
}

__device__ __forceinline__ float4 h4_to_f4(uint2 u) {
    __half2 a = *(__half2*)&u.x;
    __half2 b = *(__half2*)&u.y;
    float2 fa = __half22float2(a);
    float2 fb = __half22float2(b);
    return make_float4(fa.x, fa.y, fb.x, fb.y);
}

// ---------------- chain B: edge degree count ---------------------------------
__global__ void __launch_bounds__(256)
count_kernel(const int* __restrict__ src, const int* __restrict__ dst) {
    int e = blockIdx.x * blockDim.x + threadIdx.x;
    if (e < Ee) {
        atomicAdd(&g_degout[src[e]], 1);
        atomicAdd(&g_degin[dst[e]], 1);
    }
}

// ---------------- chain A: x column stats ------------------------------------
__global__ void __launch_bounds__(256)
stats_x_kernel(const float* __restrict__ x) {
    int t = threadIdx.x;
    int col = t & 127, half = t >> 7;
    float s = 0.f, ss = 0.f;
    for (int r = blockIdx.x * 2 + half; r < Nn; r += STAT_BLOCKS * 2) {
        float v = x[(long)r * F_IN + col];
        s += v; ss += v * v;
    }
    __shared__ float sh0[256], sh1[256];
    sh0[t] = s; sh1[t] = ss;
    __syncthreads();
    if (half == 0) {
        s += sh0[128 + col]; ss += sh1[128 + col];
        atomicAdd(&g_sum[col], s);
        atomicAdd(&g_sumsq[col], ss);
    }
}

// ---------------- scan (multi-block, 3 kernels) ------------------------------
__global__ void scan1_kernel() {
    __shared__ int sh[SCAN_T];
    int t = threadIdx.x, b = blockIdx.x;
    int s = 0;
    #pragma unroll
    for (int j = 0; j < 4; j++) {
        int i = b * SCAN_E + t + j * SCAN_T;
        if (i < Nn) s += g_degin[i];
    }
    sh[t] = s; __syncthreads();
    for (int o = SCAN_T / 2; o > 0; o >>= 1) {
        if (t < o) sh[t] += sh[t + o];
        __syncthreads();
    }
    if (t == 0) g_bsum[b] = sh[0];
}

__global__ void scan2_kernel() {
    if (threadIdx.x == 0) {
        int acc = 0;
        for (int b = 0; b < SCAN_NB; b++) { g_bbase[b] = acc; acc += g_bsum[b]; }
        g_off[Nn] = acc;
    }
}

__global__ void scan3_kernel() {   // local scan + cursor + dis
    __shared__ int sh[SCAN_T];
    int t = threadIdx.x, b = blockIdx.x;
    int base = b * SCAN_E + t * 4;
    int d0 = 0, d1 = 0, d2 = 0, d3 = 0;
    if (base + 0 < Nn) d0 = g_degin[base + 0];
    if (base + 1 < Nn) d1 = g_degin[base + 1];
    if (base + 2 < Nn) d2 = g_degin[base + 2];
    if (base + 3 < Nn) d3 = g_degin[base + 3];
    int tsum = d0 + d1 + d2 + d3;
    sh[t] = tsum; __syncthreads();
    for (int o = 1; o < SCAN_T; o <<= 1) {
        int v = (t >= o) ? sh[t - o] : 0;
        __syncthreads();
        sh[t] += v;
        __syncthreads();
    }
    int excl = sh[t] - tsum + g_bbase[b];
    int o0 = excl, o1 = o0 + d0, o2 = o1 + d1, o3 = o2 + d2;
    if (base + 0 < Nn) {
        g_off[base + 0] = o0; g_cursor[base + 0] = o0;
        g_dis[base + 0] = rsqrtf((float)(g_degout[base + 0] + 1));
    }
    if (base + 1 < Nn) {
        g_off[base + 1] = o1; g_cursor[base + 1] = o1;
        g_dis[base + 1] = rsqrtf((float)(g_degout[base + 1] + 1));
    }
    if (base + 2 < Nn) {
        g_off[base + 2] = o2; g_cursor[base + 2] = o2;
        g_dis[base + 2] = rsqrtf((float)(g_degout[base + 2] + 1));
    }
    if (base + 3 < Nn) {
        g_off[base + 3] = o3; g_cursor[base + 3] = o3;
        g_dis[base + 3] = rsqrtf((float)(g_degout[base + 3] + 1));
    }
}

// ---------------- fill CSR + restore deg zero invariant ---------------------
__global__ void __launch_bounds__(256)
fill_kernel(const int* __restrict__ src, const int* __restrict__ dst) {
    int e = blockIdx.x * blockDim.x + threadIdx.x;
    if (e < Ee) {
        int pos = atomicAdd(&g_cursor[dst[e]], 1);
        g_csr[pos] = src[e];
    }
    if (e < Nn) { g_degin[e] = 0; g_degout[e] = 0; }
}

// ---------------- fold: BN -> (Wp, c); zero accumulators --------------------
__global__ void __launch_bounds__(256)
fold_kernel(const float* __restrict__ gamma, const float* __restrict__ beta,
            const float* __restrict__ W, const float* __restrict__ blin,
            int K, int fromX) {
    __shared__ float s_s[F_IN], s_t[F_IN];
    int t = threadIdx.x;
    float* sums = fromX ? g_sum : g_s2;
    float* sqs  = fromX ? g_sumsq : g_q2;
    if (t < K) {
        float mu  = sums[t] * INVN;
        float var = fmaxf(sqs[t] * INVN - mu * mu, 0.f);
        float sc  = gamma[t] * rsqrtf(var + BN_EPS);
        s_s[t] = sc;
        s_t[t] = beta[t] - mu * sc;
        sums[t] = 0.f;
        sqs[t]  = 0.f;
    }
    __syncthreads();
    for (int i = t; i < K * HID; i += 256)
        g_Wp[i] = s_s[i >> 6] * W[i];
    if (t < HID) {
        float c = blin ? blin[t] : 0.f;
        for (int k = 0; k < K; k++) c += s_t[k] * W[k * HID + t];
        g_c[t] = c;
    }
}

// ---------------- tiled GEMM: 128x64 tile, 8x4 register tiles ---------------
template <int K, bool FEAT>
__global__ void __launch_bounds__(256, 2)
gemm_kernel(const float* __restrict__ A) {
    __shared__ float As[128 * 64];   // 32 KB
    __shared__ float Wsm[64 * 64];   // 16 KB
    const int t  = threadIdx.x;
    const int tx = t & 15;
    const int ty = t >> 4;
    const int rowBase = blockIdx.x * 128;

    float4 acc[8];
    #pragma unroll
    for (int i = 0; i < 8; i++) acc[i] = make_float4(0.f, 0.f, 0.f, 0.f);

    for (int kt = 0; kt < K; kt += 64) {
        #pragma unroll
        for (int i = t; i < 128 * 16; i += 256) {
            int r = i >> 4, c4 = i & 15;
            int gr = rowBase + r;
            float4 v = {0,0,0,0};
            if (gr < Nn) v = *(const float4*)(A + (long)gr * K + kt + 4 * c4);
            ((float4*)As)[i] = v;
        }
        #pragma unroll
        for (int i = t; i < 64 * 16; i += 256) {
            int r = i >> 4, c4 = i & 15;
            ((float4*)Wsm)[i] = *(const float4*)(g_Wp + (long)(kt + r) * 64 + 4 * c4);
        }
        __syncthreads();

        #pragma unroll
        for (int k4 = 0; k4 < 16; k4++) {
            float4 w0 = ((const float4*)Wsm)[(4 * k4 + 0) * 16 + tx];
            float4 w1 = ((const float4*)Wsm)[(4 * k4 + 1) * 16 + tx];
            float4 w2 = ((const float4*)Wsm)[(4 * k4 + 2) * 16 + tx];
            float4 w3 = ((const float4*)Wsm)[(4 * k4 + 3) * 16 + tx];
            #pragma unroll
            for (int i = 0; i < 8; i++) {
                float4 a = ((const float4*)As)[(8 * ty + i) * 16 + k4];
                acc[i].x += a.x * w0.x; acc[i].y += a.x * w0.y;
                acc[i].z += a.x * w0.z; acc[i].w += a.x * w0.w;
                acc[i].x += a.y * w1.x; acc[i].y += a.y * w1.y;
                acc[i].z += a.y * w1.z; acc[i].w += a.y * w1.w;
                acc[i].x += a.z * w2.x; acc[i].y += a.z * w2.y;
                acc[i].z += a.z * w2.z; acc[i].w += a.z * w2.w;
                acc[i].x += a.w * w3.x; acc[i].y += a.w * w3.y;
                acc[i].z += a.w * w3.z; acc[i].w += a.w * w3.w;
            }
        }
        __syncthreads();
    }

    float4 cv = *(const float4*)(g_c + 4 * tx);
    float4 ls = {0,0,0,0}, lq = {0,0,0,0};
    #pragma unroll
    for (int i = 0; i < 8; i++) {
        int gr = rowBase + 8 * ty + i;
        if (gr >= Nn) continue;
        float4 v = acc[i];
        v.x += cv.x; v.y += cv.y; v.z += cv.z; v.w += cv.w;
        if (FEAT) {
            v.x = fmaxf(v.x, 0.f); v.y = fmaxf(v.y, 0.f);
            v.z = fmaxf(v.z, 0.f); v.w = fmaxf(v.w, 0.f);
            *(float4*)(g_h + (long)gr * 64 + 4 * tx) = v;
            ls.x += v.x; ls.y += v.y; ls.z += v.z; ls.w += v.w;
            lq.x += v.x * v.x; lq.y += v.y * v.y;
            lq.z += v.z * v.z; lq.w += v.w * v.w;
        } else {
            float di = __ldg(g_dis + gr);
            __half2 p0 = __floats2half2_rn(di * v.x, di * v.y);
            __half2 p1 = __floats2half2_rn(di * v.z, di * v.w);
            uint2 u;
            u.x = *(unsigned*)&p0;
            u.y = *(unsigned*)&p1;
            *(uint2*)(g_zh + (long)gr * 64 + 4 * tx) = u;
        }
    }
    if (FEAT) {
        __syncthreads();
        ((float4*)As)[t]       = ls;
        ((float4*)As)[256 + t] = lq;
        __syncthreads();
        if (ty == 0) {
            #pragma unroll
            for (int j = 1; j < 16; j++) {
                float4 a = ((float4*)As)[j * 16 + tx];
                float4 b = ((float4*)As)[256 + j * 16 + tx];
                ls.x += a.x; ls.y += a.y; ls.z += a.z; ls.w += a.w;
                lq.x += b.x; lq.y += b.y; lq.z += b.z; lq.w += b.w;
            }
            red_add_v4(g_s2 + 4 * tx, ls);
            red_add_v4(g_q2 + 4 * tx, lq);
        }
    }
}

// ---------------- CSR gather aggregation (fp16 zs, pre-scaled) --------------
template <int MODE>
__global__ void __launch_bounds__(256)
gather_kernel(const float* __restrict__ bias,
              const int* __restrict__ batch,
              float* __restrict__ gout) {
    const int t    = threadIdx.x;
    const int c    = t & 15;
    const int slot = t >> 4;
    const int i    = blockIdx.x * 16 + slot;
    float4 b4 = *(const float4*)(bias + 4 * c);
    float4 ls = {0,0,0,0}, lq = {0,0,0,0};

    if (i < Nn) {
        int st = __ldg(g_off + i), en = __ldg(g_off + i + 1);
        float di = __ldg(g_dis + i);
        const __half* zb = g_zh;
        float4 acc = h4_to_f4(__ldg((const uint2*)(zb + (long)i * 64) + c));
        int e = st;
        for (; e + 3 < en; e += 4) {
            int s0 = __ldg(g_csr + e + 0);
            int s1 = __ldg(g_csr + e + 1);
            int s2 = __ldg(g_csr + e + 2);
            int s3 = __ldg(g_csr + e + 3);
            uint2 u0 = __ldg((const uint2*)(zb + (long)s0 * 64) + c);
            uint2 u1 = __ldg((const uint2*)(zb + (long)s1 * 64) + c);
            uint2 u2 = __ldg((const uint2*)(zb + (long)s2 * 64) + c);
            uint2 u3 = __ldg((const uint2*)(zb + (long)s3 * 64) + c);
            float4 v0 = h4_to_f4(u0), v1 = h4_to_f4(u1);
            float4 v2 = h4_to_f4(u2), v3 = h4_to_f4(u3);
            acc.x += v0.x + v1.x + v2.x + v3.x;
            acc.y += v0.y + v1.y + v2.y + v3.y;
            acc.z += v0.z + v1.z + v2.z + v3.z;
            acc.w += v0.w + v1.w + v2.w + v3.w;
        }
        for (; e < en; e++) {
            int s = __ldg(g_csr + e);
            float4 v = h4_to_f4(__ldg((const uint2*)(zb + (long)s * 64) + c));
            acc.x += v.x; acc.y += v.y; acc.z += v.z; acc.w += v.w;
        }
        float4 h;
        h.x = fmaxf(di * acc.x + b4.x, 0.f);
        h.y = fmaxf(di * acc.y + b4.y, 0.f);
        h.z = fmaxf(di * acc.z + b4.z, 0.f);
        h.w = fmaxf(di * acc.w + b4.w, 0.f);
        if (MODE == 0) {
            *(float4*)(g_h + (long)i * 64 + 4 * c) = h;
            ls = h;
            lq.x = h.x * h.x; lq.y = h.y * h.y;
            lq.z = h.z * h.z; lq.w = h.w * h.w;
        } else {
            int g = __ldg(batch + i);
            red_add_v4(gout + (long)g * 64 + 4 * c, h);
        }
    }

    if (MODE == 0) {
        __shared__ float4 shS[256], shQ[256];
        shS[t] = ls; shQ[t] = lq;
        __syncthreads();
        if (slot == 0) {
            #pragma unroll
            for (int j = 1; j < 16; j++) {
                float4 a = shS[j * 16 + c], b = shQ[j * 16 + c];
                ls.x += a.x; ls.y += a.y; ls.z += a.z; ls.w += a.w;
                lq.x += b.x; lq.y += b.y; lq.z += b.z; lq.w += b.w;
            }
            red_add_v4(g_s2 + 4 * c, ls);
            red_add_v4(g_q2 + 4 * c, lq);
        }
    }
}

// ---------------- host-side symbol / stream resolution ----------------------
static float* sym_h() {
    static float* p = nullptr;
    if (!p) cudaGetSymbolAddress((void**)&p, g_h);
    return p;
}

// ---------------- launch ------------------------------------------------------
extern "C" void kernel_launch(void* const* d_in, const int* in_sizes, int n_in,
                              void* d_out, int out_size) {
    const float* x         = (const float*)d_in[0];
    const int*   ei        = (const int*)d_in[1];
    const int*   src       = ei;
    const int*   dst       = ei + Ee;
    const int*   batch     = (const int*)d_in[2];
    const float* bn_feat_g = (const float*)d_in[3];
    const float* bn_feat_b = (const float*)d_in[4];
    const float* W_feat    = (const float*)d_in[5];
    const float* b_feat    = (const float*)d_in[6];
    const float* bn_g      = (const float*)d_in[7];
    const float* bn_b      = (const float*)d_in[8];
    const float* Ws        = (const float*)d_in[9];
    const float* bs        = (const float*)d_in[10];
    float* gout = (float*)d_out;

    // second stream + fork/join events (created once; host-side only)
    static cudaStream_t s2 = nullptr;
    static cudaEvent_t e0 = nullptr, eDis = nullptr, eCsr = nullptr;
    if (!s2) {
        cudaStreamCreateWithFlags(&s2, cudaStreamNonBlocking);
        cudaEventCreateWithFlags(&e0,   cudaEventDisableTiming);
        cudaEventCreateWithFlags(&eDis, cudaEventDisableTiming);
        cudaEventCreateWithFlags(&eCsr, cudaEventDisableTiming);
    }

    // ---- fork: chain B (CSR build + dis) on s2 ----
    cudaEventRecord(e0, 0);
    cudaStreamWaitEvent(s2, e0, 0);
    count_kernel<<<EDGE_BLOCKS, 256, 0, s2>>>(src, dst);
    scan1_kernel<<<SCAN_NB, SCAN_T, 0, s2>>>();
    scan2_kernel<<<1, 32, 0, s2>>>();
    scan3_kernel<<<SCAN_NB, SCAN_T, 0, s2>>>();
    cudaEventRecord(eDis, s2);                      // g_dis + g_off ready
    fill_kernel<<<EDGE_BLOCKS, 256, 0, s2>>>(src, dst);
    cudaEventRecord(eCsr, s2);                      // g_csr ready

    // ---- chain A on main stream ----
    stats_x_kernel<<<STAT_BLOCKS, 256>>>(x);
    fold_kernel<<<1, 256>>>(bn_feat_g, bn_feat_b, W_feat, b_feat, F_IN, 1);
    gemm_kernel<F_IN, true><<<GEMM_BLOCKS, 256>>>(x);
    cudaMemsetAsync(gout, 0, (size_t)Gg * HID * sizeof(float));

    for (int i = 0; i < Ll; i++) {
        fold_kernel<<<1, 256>>>(bn_g + i * HID, bn_b + i * HID,
                                Ws + (long)i * HID * HID, nullptr, HID, 0);
        if (i == 0) cudaStreamWaitEvent(0, eDis, 0);   // gemm epilogue needs dis
        gemm_kernel<HID, false><<<GEMM_BLOCKS, 256>>>(sym_h());
        if (i == 0) cudaStreamWaitEvent(0, eCsr, 0);   // gather needs CSR
        if (i < Ll - 1)
            gather_kernel<0><<<GATHER_GRID, 256>>>(bs + i * HID, nullptr,
                                                   nullptr);
        else
            gather_kernel<1><<<GATHER_GRID, 256>>>(bs + i * HID, batch, gout);
    }
}